// round 4
// baseline (speedup 1.0000x reference)
#include <cuda_runtime.h>

#define NN 50000
#define EE 1600000
#define DD 128
#define GG 64
#define LL 3

// ---------------- scratch (static device globals; no allocation) ----------------
__device__ float g_bufA[NN * DD];   // ping-pong node features
__device__ float g_bufB[NN * DD];
__device__ float g_Sd[NN * DD];     // per-node sum of X[src] over data edges
__device__ float g_Sc[NN * DD];     // per-node sum over ctrl edges
__device__ int   g_cntd[NN];
__device__ int   g_cntc[NN];
__device__ int   g_rowptr[NN + 1];
__device__ int   g_cursor[NN];
__device__ unsigned int g_edge[EE]; // src | (type<<31), sorted by dst

// ---------------- f32x2 packed helper ----------------
__device__ __forceinline__ unsigned long long ffma2(unsigned long long a,
                                                    unsigned long long b,
                                                    unsigned long long c) {
    unsigned long long d;
    asm("fma.rn.f32x2 %0, %1, %2, %3;" : "=l"(d) : "l"(a), "l"(b), "l"(c));
    return d;
}

// ---------------- CSR build ----------------
__global__ void k_zero_counts() {
    int i = blockIdx.x * blockDim.x + threadIdx.x;
    if (i < NN) { g_cntd[i] = 0; g_cntc[i] = 0; }
}

__global__ void k_count(const int* __restrict__ dst, const int* __restrict__ et) {
    int e = blockIdx.x * blockDim.x + threadIdx.x;
    if (e < EE) {
        int d = dst[e];
        if (et[e] == 0) atomicAdd(&g_cntd[d], 1);
        else            atomicAdd(&g_cntc[d], 1);
    }
}

__global__ void __launch_bounds__(1024) k_scan() {
    __shared__ int warp_sums[32];
    __shared__ int s_carry;
    int tid = threadIdx.x;
    int lane = tid & 31, wid = tid >> 5;
    if (tid == 0) s_carry = 0;
    __syncthreads();
    for (int base = 0; base < NN; base += 1024) {
        int i = base + tid;
        int v = (i < NN) ? (g_cntd[i] + g_cntc[i]) : 0;
        int x = v;
        #pragma unroll
        for (int off = 1; off < 32; off <<= 1) {
            int y = __shfl_up_sync(0xffffffffu, x, off);
            if (lane >= off) x += y;
        }
        if (lane == 31) warp_sums[wid] = x;
        __syncthreads();
        if (tid < 32) {
            int w = warp_sums[tid];
            #pragma unroll
            for (int off = 1; off < 32; off <<= 1) {
                int y = __shfl_up_sync(0xffffffffu, w, off);
                if (tid >= off) w += y;
            }
            warp_sums[tid] = w;
        }
        __syncthreads();
        int woff = (wid > 0) ? warp_sums[wid - 1] : 0;
        int incl = x + woff;
        if (i < NN) {
            int rp = s_carry + incl - v;
            g_rowptr[i] = rp;
            g_cursor[i] = rp;
        }
        int total = warp_sums[31];
        __syncthreads();
        if (tid == 0) s_carry += total;
        __syncthreads();
    }
    if (tid == 0) g_rowptr[NN] = s_carry;
}

__global__ void k_fill(const int* __restrict__ src, const int* __restrict__ dst,
                       const int* __restrict__ et) {
    int e = blockIdx.x * blockDim.x + threadIdx.x;
    if (e < EE) {
        int d = dst[e];
        int pos = atomicAdd(&g_cursor[d], 1);
        g_edge[pos] = (unsigned int)src[e] | ((unsigned int)et[e] << 31);
    }
}

// ---------------- edge aggregation: warp per dst node ----------------
__global__ void __launch_bounds__(256) k_aggregate(const float* __restrict__ X) {
    int w = (blockIdx.x * blockDim.x + threadIdx.x) >> 5;
    int lane = threadIdx.x & 31;
    if (w >= NN) return;
    int beg = g_rowptr[w], end = g_rowptr[w + 1];
    const float4* X4 = (const float4*)X;
    float4 ad = make_float4(0.f, 0.f, 0.f, 0.f);
    float4 ac = make_float4(0.f, 0.f, 0.f, 0.f);
    int j = beg;
    for (; j + 1 < end; j += 2) {
        unsigned int e0 = g_edge[j];
        unsigned int e1 = g_edge[j + 1];
        float4 v0 = __ldg(X4 + (int)(e0 & 0x7fffffffu) * 32 + lane);
        float4 v1 = __ldg(X4 + (int)(e1 & 0x7fffffffu) * 32 + lane);
        if (e0 >> 31) { ac.x += v0.x; ac.y += v0.y; ac.z += v0.z; ac.w += v0.w; }
        else          { ad.x += v0.x; ad.y += v0.y; ad.z += v0.z; ad.w += v0.w; }
        if (e1 >> 31) { ac.x += v1.x; ac.y += v1.y; ac.z += v1.z; ac.w += v1.w; }
        else          { ad.x += v1.x; ad.y += v1.y; ad.z += v1.z; ad.w += v1.w; }
    }
    if (j < end) {
        unsigned int e0 = g_edge[j];
        float4 v0 = __ldg(X4 + (int)(e0 & 0x7fffffffu) * 32 + lane);
        if (e0 >> 31) { ac.x += v0.x; ac.y += v0.y; ac.z += v0.z; ac.w += v0.w; }
        else          { ad.x += v0.x; ad.y += v0.y; ad.z += v0.z; ad.w += v0.w; }
    }
    ((float4*)g_Sd)[w * 32 + lane] = ad;
    ((float4*)g_Sc)[w * 32 + lane] = ac;
}

// ---------------- big-tile triple GEMM + bias + relu ----------------
// One logical GEMM: Y = relu([Sd|Sc|X] @ [Wd;Wc;Ws] + cntd*bd + cntc*bc + bs)
// Block: 128 rows x 128 cols, 256 threads, thread tile 8x8, K-tile 32.
// sA: [k][rowpair] float2 (pre-paired rows -> LDS gives packed f32x2 operand)
// sW: [k][col] float2 duplicated (w,w) -> LDS gives packed multiplicand, no movs.
__global__ void __launch_bounds__(256, 2) k_gemm(
    const float* __restrict__ Xin,
    const float* __restrict__ Wd, const float* __restrict__ bd,
    const float* __restrict__ Wc, const float* __restrict__ bc,
    const float* __restrict__ Ws, const float* __restrict__ bs,
    float* __restrict__ Y)
{
    __shared__ __align__(16) float2 sA[32][64];   // 16KB
    __shared__ __align__(16) float2 sW[32][128];  // 32KB

    int tid = threadIdx.x;
    int rowbase = blockIdx.x * 128;
    int tr = tid >> 4;   // 0..15 -> rows tr*8 .. tr*8+7
    int tc = tid & 15;   // 0..15 -> cols tc*8 .. tc*8+7

    const float* Aseg[3] = { g_Sd, g_Sc, Xin };
    const float* Wseg[3] = { Wd, Wc, Ws };

    unsigned long long acc[4][8];
    #pragma unroll
    for (int i = 0; i < 4; i++)
        #pragma unroll
        for (int c = 0; c < 8; c++) acc[i][c] = 0ull;

    // A-load mapping: 2 threads per row, 16 k each
    int lrow = tid >> 1;            // 0..127
    int halfk = (tid & 1) * 16;

    #pragma unroll 1
    for (int seg = 0; seg < 3; seg++) {
        const float* Ap = Aseg[seg];
        const float* Wp = Wseg[seg];
        #pragma unroll 1
        for (int kt = 0; kt < 4; kt++) {
            int k0 = kt * 32;
            __syncthreads();
            // ---- load A tile (transposed, row-paired) ----
            {
                int grow = rowbase + lrow;
                int rp = lrow >> 1;
                const float4* src = (const float4*)(Ap + grow * DD + k0 + halfk);
                #pragma unroll
                for (int j = 0; j < 4; j++) {
                    float4 v = (grow < NN) ? __ldg(src + j)
                                           : make_float4(0.f, 0.f, 0.f, 0.f);
                    int kk = halfk + j * 4;
                    if (lrow & 1) {
                        sA[kk + 0][rp].y = v.x; sA[kk + 1][rp].y = v.y;
                        sA[kk + 2][rp].y = v.z; sA[kk + 3][rp].y = v.w;
                    } else {
                        sA[kk + 0][rp].x = v.x; sA[kk + 1][rp].x = v.y;
                        sA[kk + 2][rp].x = v.z; sA[kk + 3][rp].x = v.w;
                    }
                }
            }
            // ---- load W tile (duplicated) ----
            #pragma unroll
            for (int i = 0; i < 4; i++) {
                int F = tid + 256 * i;       // float4 index 0..1023
                int kk = F >> 5;
                int n4 = F & 31;
                float4 w = __ldg((const float4*)(Wp + (k0 + kk) * DD) + n4);
                sW[kk][n4 * 4 + 0] = make_float2(w.x, w.x);
                sW[kk][n4 * 4 + 1] = make_float2(w.y, w.y);
                sW[kk][n4 * 4 + 2] = make_float2(w.z, w.z);
                sW[kk][n4 * 4 + 3] = make_float2(w.w, w.w);
            }
            __syncthreads();
            // ---- compute ----
            #pragma unroll 4
            for (int k = 0; k < 32; k++) {
                const ulonglong2* ap = (const ulonglong2*)&sA[k][tr * 4];
                ulonglong2 p0 = ap[0], p1 = ap[1];
                unsigned long long xa0 = p0.x, xa1 = p0.y;
                unsigned long long xa2 = p1.x, xa3 = p1.y;
                const ulonglong2* wp = (const ulonglong2*)&sW[k][tc * 8];
                ulonglong2 q0 = wp[0], q1 = wp[1], q2 = wp[2], q3 = wp[3];
                unsigned long long wv[8] = { q0.x, q0.y, q1.x, q1.y,
                                             q2.x, q2.y, q3.x, q3.y };
                #pragma unroll
                for (int c = 0; c < 8; c++) {
                    acc[0][c] = ffma2(xa0, wv[c], acc[0][c]);
                    acc[1][c] = ffma2(xa1, wv[c], acc[1][c]);
                    acc[2][c] = ffma2(xa2, wv[c], acc[2][c]);
                    acc[3][c] = ffma2(xa3, wv[c], acc[3][c]);
                }
            }
        }
    }

    // ---- epilogue: bias + relu + store ----
    float bdv[8], bcv[8], bsv[8];
    *(float4*)&bdv[0] = __ldg((const float4*)bd + tc * 2);
    *(float4*)&bdv[4] = __ldg((const float4*)bd + tc * 2 + 1);
    *(float4*)&bcv[0] = __ldg((const float4*)bc + tc * 2);
    *(float4*)&bcv[4] = __ldg((const float4*)bc + tc * 2 + 1);
    *(float4*)&bsv[0] = __ldg((const float4*)bs + tc * 2);
    *(float4*)&bsv[4] = __ldg((const float4*)bs + tc * 2 + 1);

    #pragma unroll
    for (int r = 0; r < 8; r++) {
        int row = rowbase + tr * 8 + r;
        if (row >= NN) continue;
        int rp = r >> 1;
        int hi = r & 1;
        float cd = (float)g_cntd[row];
        float cc = (float)g_cntc[row];
        float o[8];
        #pragma unroll
        for (int c = 0; c < 8; c++) {
            float2 f = *(float2*)&acc[rp][c];
            float v = hi ? f.y : f.x;
            o[c] = fmaxf(fmaf(cd, bdv[c], fmaf(cc, bcv[c], v + bsv[c])), 0.f);
        }
        float4* dst = (float4*)(Y + row * DD + tc * 8);
        dst[0] = make_float4(o[0], o[1], o[2], o[3]);
        dst[1] = make_float4(o[4], o[5], o[6], o[7]);
    }
}

// ---------------- mean pool per graph (batch_ids sorted) ----------------
__global__ void __launch_bounds__(DD) k_pool(const float* __restrict__ X,
                                             const int* __restrict__ batch,
                                             float* __restrict__ out) {
    int g = blockIdx.x;
    int c = threadIdx.x;
    int lo = 0, hi = NN;
    while (lo < hi) { int m = (lo + hi) >> 1; if (batch[m] < g) lo = m + 1; else hi = m; }
    int start = lo;
    lo = start; hi = NN;
    while (lo < hi) { int m = (lo + hi) >> 1; if (batch[m] < g + 1) lo = m + 1; else hi = m; }
    int end = lo;

    float s0 = 0.f, s1 = 0.f, s2 = 0.f, s3 = 0.f;
    int n = start;
    for (; n + 3 < end; n += 4) {
        s0 += X[(n + 0) * DD + c];
        s1 += X[(n + 1) * DD + c];
        s2 += X[(n + 2) * DD + c];
        s3 += X[(n + 3) * DD + c];
    }
    for (; n < end; n++) s0 += X[n * DD + c];
    float s = (s0 + s1) + (s2 + s3);
    float cnt = (float)(end - start);
    out[g * DD + c] = s / fmaxf(cnt, 1.0f);
}

// ---------------- launch ----------------
extern "C" void kernel_launch(void* const* d_in, const int* in_sizes, int n_in,
                              void* d_out, int out_size) {
    const float* X  = (const float*)d_in[0];
    const float* Wd = (const float*)d_in[1];
    const float* bd = (const float*)d_in[2];
    const float* Wc = (const float*)d_in[3];
    const float* bc = (const float*)d_in[4];
    const float* Ws = (const float*)d_in[5];
    const float* bs = (const float*)d_in[6];
    const int* ei   = (const int*)d_in[7];
    const int* et   = (const int*)d_in[8];
    const int* bid  = (const int*)d_in[9];
    const int* srcp = ei;
    const int* dstp = ei + EE;

    void* pA = nullptr;
    void* pB = nullptr;
    cudaGetSymbolAddress(&pA, g_bufA);
    cudaGetSymbolAddress(&pB, g_bufB);
    float* A = (float*)pA;
    float* B = (float*)pB;

    // CSR build (graph identical across layers -> built once per call)
    k_zero_counts<<<(NN + 255) / 256, 256>>>();
    k_count<<<(EE + 255) / 256, 256>>>(dstp, et);
    k_scan<<<1, 1024>>>();
    k_fill<<<(EE + 255) / 256, 256>>>(srcp, dstp, et);

    const float* cur = X;
    float* outs[3] = { A, B, A };
    for (int l = 0; l < LL; l++) {
        k_aggregate<<<(NN * 32 + 255) / 256, 256>>>(cur);
        k_gemm<<<(NN + 127) / 128, 256>>>(cur,
                                          Wd + l * DD * DD, bd + l * DD,
                                          Wc + l * DD * DD, bc + l * DD,
                                          Ws + l * DD * DD, bs + l * DD,
                                          outs[l]);
        cur = outs[l];
    }
    k_pool<<<GG, DD>>>(cur, bid, (float*)d_out);
}

// round 5
// speedup vs baseline: 1.4747x; 1.4747x over previous
#include <cuda_runtime.h>

#define NN 50000
#define EE 1600000
#define DD 128
#define GG 64
#define LL 3

// ---------------- scratch (static device globals; no allocation) ----------------
__device__ float g_bufA[NN * DD];   // ping-pong node features
__device__ float g_bufB[NN * DD];
__device__ float g_Sd[NN * DD];     // per-node sum of X[src] over data edges
__device__ float g_Sc[NN * DD];     // per-node sum over ctrl edges
__device__ int   g_cntd[NN];
__device__ int   g_cntc[NN];
__device__ int   g_rowptr[NN + 1];
__device__ int   g_cursor[NN];
__device__ unsigned int g_edge[EE]; // src | (type<<31), sorted by dst

// ---------------- f32x2 packed helper ----------------
__device__ __forceinline__ unsigned long long ffma2(unsigned long long a,
                                                    unsigned long long b,
                                                    unsigned long long c) {
    unsigned long long d;
    asm("fma.rn.f32x2 %0, %1, %2, %3;" : "=l"(d) : "l"(a), "l"(b), "l"(c));
    return d;
}

// ---------------- CSR build ----------------
__global__ void k_zero_counts() {
    int i = blockIdx.x * blockDim.x + threadIdx.x;
    if (i < NN) { g_cntd[i] = 0; g_cntc[i] = 0; }
}

__global__ void k_count(const int* __restrict__ dst, const int* __restrict__ et) {
    int e = blockIdx.x * blockDim.x + threadIdx.x;
    if (e < EE) {
        int d = dst[e];
        if (et[e] == 0) atomicAdd(&g_cntd[d], 1);
        else            atomicAdd(&g_cntc[d], 1);
    }
}

__global__ void __launch_bounds__(1024) k_scan() {
    __shared__ int warp_sums[32];
    __shared__ int s_carry;
    int tid = threadIdx.x;
    int lane = tid & 31, wid = tid >> 5;
    if (tid == 0) s_carry = 0;
    __syncthreads();
    for (int base = 0; base < NN; base += 1024) {
        int i = base + tid;
        int v = (i < NN) ? (g_cntd[i] + g_cntc[i]) : 0;
        int x = v;
        #pragma unroll
        for (int off = 1; off < 32; off <<= 1) {
            int y = __shfl_up_sync(0xffffffffu, x, off);
            if (lane >= off) x += y;
        }
        if (lane == 31) warp_sums[wid] = x;
        __syncthreads();
        if (tid < 32) {
            int w = warp_sums[tid];
            #pragma unroll
            for (int off = 1; off < 32; off <<= 1) {
                int y = __shfl_up_sync(0xffffffffu, w, off);
                if (tid >= off) w += y;
            }
            warp_sums[tid] = w;
        }
        __syncthreads();
        int woff = (wid > 0) ? warp_sums[wid - 1] : 0;
        int incl = x + woff;
        if (i < NN) {
            int rp = s_carry + incl - v;
            g_rowptr[i] = rp;
            g_cursor[i] = rp;
        }
        int total = warp_sums[31];
        __syncthreads();
        if (tid == 0) s_carry += total;
        __syncthreads();
    }
    if (tid == 0) g_rowptr[NN] = s_carry;
}

__global__ void k_fill(const int* __restrict__ src, const int* __restrict__ dst,
                       const int* __restrict__ et) {
    int e = blockIdx.x * blockDim.x + threadIdx.x;
    if (e < EE) {
        int d = dst[e];
        int pos = atomicAdd(&g_cursor[d], 1);
        g_edge[pos] = (unsigned int)src[e] | ((unsigned int)et[e] << 31);
    }
}

// ---------------- edge aggregation: warp per dst node ----------------
__global__ void __launch_bounds__(256) k_aggregate(const float* __restrict__ X) {
    int w = (blockIdx.x * blockDim.x + threadIdx.x) >> 5;
    int lane = threadIdx.x & 31;
    if (w >= NN) return;
    int beg = g_rowptr[w], end = g_rowptr[w + 1];
    const float4* X4 = (const float4*)X;
    float4 ad = make_float4(0.f, 0.f, 0.f, 0.f);
    float4 ac = make_float4(0.f, 0.f, 0.f, 0.f);
    int j = beg;
    for (; j + 1 < end; j += 2) {
        unsigned int e0 = g_edge[j];
        unsigned int e1 = g_edge[j + 1];
        float4 v0 = __ldg(X4 + (int)(e0 & 0x7fffffffu) * 32 + lane);
        float4 v1 = __ldg(X4 + (int)(e1 & 0x7fffffffu) * 32 + lane);
        if (e0 >> 31) { ac.x += v0.x; ac.y += v0.y; ac.z += v0.z; ac.w += v0.w; }
        else          { ad.x += v0.x; ad.y += v0.y; ad.z += v0.z; ad.w += v0.w; }
        if (e1 >> 31) { ac.x += v1.x; ac.y += v1.y; ac.z += v1.z; ac.w += v1.w; }
        else          { ad.x += v1.x; ad.y += v1.y; ad.z += v1.z; ad.w += v1.w; }
    }
    if (j < end) {
        unsigned int e0 = g_edge[j];
        float4 v0 = __ldg(X4 + (int)(e0 & 0x7fffffffu) * 32 + lane);
        if (e0 >> 31) { ac.x += v0.x; ac.y += v0.y; ac.z += v0.z; ac.w += v0.w; }
        else          { ad.x += v0.x; ad.y += v0.y; ad.z += v0.z; ad.w += v0.w; }
    }
    ((float4*)g_Sd)[w * 32 + lane] = ad;
    ((float4*)g_Sc)[w * 32 + lane] = ac;
}

// ---------------- triple GEMM + bias + relu (mov-free inner loop) ----------------
// Y = relu(Sd@Wd + Sc@Wc + X@Ws + cntd*bd + cntc*bc + bs)
// Block: 32 rows x 128 cols, 256 threads. Thread (tx,ty): cols tx*4..+3,
// rows ty*4..+3. Matrices processed sequentially through one duplicated
// smem X tile: sX[k][row] = (x,x) so LDS.128 yields packed f32x2 operands.
// W row LDG.128 yields two packed column-pair multiplicands directly.
__global__ void __launch_bounds__(256) k_gemm(
    const float* __restrict__ Xin,
    const float* __restrict__ Wd, const float* __restrict__ bd,
    const float* __restrict__ Wc, const float* __restrict__ bc,
    const float* __restrict__ Ws, const float* __restrict__ bs,
    float* __restrict__ Y)
{
    __shared__ __align__(16) float2 sX[DD][32];   // 32KB, duplicated (x,x)
    int tid = threadIdx.x;
    int lane = tid & 31;
    int rowbase = blockIdx.x * 32;
    int tx = lane;
    int ty = tid >> 5;

    const float* Aseg[3] = { g_Sd, g_Sc, Xin };
    const float* Wseg[3] = { Wd, Wc, Ws };

    // acc[r][p]: row ty*4+r, column pair (tx*4 + 2p, tx*4 + 2p + 1)
    unsigned long long acc[4][2];
    #pragma unroll
    for (int r = 0; r < 4; r++) { acc[r][0] = 0ull; acc[r][1] = 0ull; }

    #pragma unroll 1
    for (int m = 0; m < 3; m++) {
        // ---- load tile (k-major, duplicated) ----
        __syncthreads();
        {
            int r = lane;
            int kq = tid >> 5; // 0..7 -> 16 k each
            int row = rowbase + r;
            const float4* src4 = (const float4*)(Aseg[m] + row * DD);
            #pragma unroll
            for (int q = 0; q < 4; q++) {
                float4 a = (row < NN) ? __ldg(src4 + kq * 4 + q)
                                      : make_float4(0.f, 0.f, 0.f, 0.f);
                int k0 = kq * 16 + q * 4;
                sX[k0 + 0][r] = make_float2(a.x, a.x);
                sX[k0 + 1][r] = make_float2(a.y, a.y);
                sX[k0 + 2][r] = make_float2(a.z, a.z);
                sX[k0 + 3][r] = make_float2(a.w, a.w);
            }
        }
        __syncthreads();

        // ---- compute ----
        const float4* Wp4 = (const float4*)Wseg[m];
        #pragma unroll 4
        for (int k = 0; k < DD; k++) {
            float4 wv = __ldg(Wp4 + k * 32 + tx);
            ulonglong2 wp = *(ulonglong2*)&wv;   // (w0,w1) (w2,w3) packed pairs
            const ulonglong2* xp = (const ulonglong2*)&sX[k][ty * 4];
            ulonglong2 x01 = xp[0];              // rows ty*4, ty*4+1 (dup'd)
            ulonglong2 x23 = xp[1];              // rows ty*4+2, ty*4+3
            acc[0][0] = ffma2(x01.x, wp.x, acc[0][0]);
            acc[0][1] = ffma2(x01.x, wp.y, acc[0][1]);
            acc[1][0] = ffma2(x01.y, wp.x, acc[1][0]);
            acc[1][1] = ffma2(x01.y, wp.y, acc[1][1]);
            acc[2][0] = ffma2(x23.x, wp.x, acc[2][0]);
            acc[2][1] = ffma2(x23.x, wp.y, acc[2][1]);
            acc[3][0] = ffma2(x23.y, wp.x, acc[3][0]);
            acc[3][1] = ffma2(x23.y, wp.y, acc[3][1]);
        }
    }

    // ---- epilogue: bias + relu + store ----
    float4 bdv = __ldg((const float4*)bd + tx);
    float4 bcv = __ldg((const float4*)bc + tx);
    float4 bsv = __ldg((const float4*)bs + tx);
    #pragma unroll
    for (int r = 0; r < 4; r++) {
        int row = rowbase + ty * 4 + r;
        if (row >= NN) continue;
        float2 c01 = *(float2*)&acc[r][0];
        float2 c23 = *(float2*)&acc[r][1];
        float cd = (float)g_cntd[row];
        float cc = (float)g_cntc[row];
        float4 o;
        o.x = fmaxf(fmaf(cd, bdv.x, fmaf(cc, bcv.x, c01.x + bsv.x)), 0.f);
        o.y = fmaxf(fmaf(cd, bdv.y, fmaf(cc, bcv.y, c01.y + bsv.y)), 0.f);
        o.z = fmaxf(fmaf(cd, bdv.z, fmaf(cc, bcv.z, c23.x + bsv.z)), 0.f);
        o.w = fmaxf(fmaf(cd, bdv.w, fmaf(cc, bcv.w, c23.y + bsv.w)), 0.f);
        ((float4*)Y)[row * 32 + tx] = o;
    }
}

// ---------------- mean pool per graph (batch_ids sorted) ----------------
__global__ void __launch_bounds__(DD) k_pool(const float* __restrict__ X,
                                             const int* __restrict__ batch,
                                             float* __restrict__ out) {
    int g = blockIdx.x;
    int c = threadIdx.x;
    int lo = 0, hi = NN;
    while (lo < hi) { int m = (lo + hi) >> 1; if (batch[m] < g) lo = m + 1; else hi = m; }
    int start = lo;
    lo = start; hi = NN;
    while (lo < hi) { int m = (lo + hi) >> 1; if (batch[m] < g + 1) lo = m + 1; else hi = m; }
    int end = lo;

    float s0 = 0.f, s1 = 0.f, s2 = 0.f, s3 = 0.f;
    int n = start;
    for (; n + 3 < end; n += 4) {
        s0 += X[(n + 0) * DD + c];
        s1 += X[(n + 1) * DD + c];
        s2 += X[(n + 2) * DD + c];
        s3 += X[(n + 3) * DD + c];
    }
    for (; n < end; n++) s0 += X[n * DD + c];
    float s = (s0 + s1) + (s2 + s3);
    float cnt = (float)(end - start);
    out[g * DD + c] = s / fmaxf(cnt, 1.0f);
}

// ---------------- launch ----------------
extern "C" void kernel_launch(void* const* d_in, const int* in_sizes, int n_in,
                              void* d_out, int out_size) {
    const float* X  = (const float*)d_in[0];
    const float* Wd = (const float*)d_in[1];
    const float* bd = (const float*)d_in[2];
    const float* Wc = (const float*)d_in[3];
    const float* bc = (const float*)d_in[4];
    const float* Ws = (const float*)d_in[5];
    const float* bs = (const float*)d_in[6];
    const int* ei   = (const int*)d_in[7];
    const int* et   = (const int*)d_in[8];
    const int* bid  = (const int*)d_in[9];
    const int* srcp = ei;
    const int* dstp = ei + EE;

    void* pA = nullptr;
    void* pB = nullptr;
    cudaGetSymbolAddress(&pA, g_bufA);
    cudaGetSymbolAddress(&pB, g_bufB);
    float* A = (float*)pA;
    float* B = (float*)pB;

    // CSR build (graph identical across layers -> built once per call)
    k_zero_counts<<<(NN + 255) / 256, 256>>>();
    k_count<<<(EE + 255) / 256, 256>>>(dstp, et);
    k_scan<<<1, 1024>>>();
    k_fill<<<(EE + 255) / 256, 256>>>(srcp, dstp, et);

    const float* cur = X;
    float* outs[3] = { A, B, A };
    for (int l = 0; l < LL; l++) {
        k_aggregate<<<(NN * 32 + 255) / 256, 256>>>(cur);
        k_gemm<<<(NN + 31) / 32, 256>>>(cur,
                                        Wd + l * DD * DD, bd + l * DD,
                                        Wc + l * DD * DD, bc + l * DD,
                                        Ws + l * DD * DD, bs + l * DD,
                                        outs[l]);
        cur = outs[l];
    }
    k_pool<<<GG, DD>>>(cur, bid, (float*)d_out);
}

// round 6
// speedup vs baseline: 1.9231x; 1.3040x over previous
#include <cuda_runtime.h>

#define NN 50000
#define EE 1600000
#define DD 128
#define GG 64
#define LL 3

// ---------------- scratch (static device globals; no allocation) ----------------
__device__ float g_bufA[NN * DD];   // ping-pong node features
__device__ float g_bufB[NN * DD];
__device__ float g_Sd[NN * DD];     // per-node sum of X[src] over data edges
__device__ float g_Sc[NN * DD];     // per-node sum over ctrl edges
__device__ int   g_cntd[NN];        // zero at entry (zeroed by k_pool tail)
__device__ int   g_cntc[NN];
__device__ int   g_rowptr[NN + 1];
__device__ int   g_cursor[NN];
__device__ unsigned int g_edge[EE]; // src | (type<<31), sorted by dst

// ---------------- f32x2 packed helpers ----------------
__device__ __forceinline__ unsigned long long ffma2(unsigned long long a,
                                                    unsigned long long b,
                                                    unsigned long long c) {
    unsigned long long d;
    asm("fma.rn.f32x2 %0, %1, %2, %3;" : "=l"(d) : "l"(a), "l"(b), "l"(c));
    return d;
}
__device__ __forceinline__ unsigned long long pk2(float v) {
    unsigned long long d;
    unsigned int u = __float_as_uint(v);
    asm("mov.b64 %0, {%1, %2};" : "=l"(d) : "r"(u), "r"(u));
    return d;
}

// ---------------- CSR build ----------------
// NOTE: g_cntd/g_cntc are guaranteed zero on entry: statics are
// zero-initialized at load, and k_pool (always the last launch of each call)
// re-zeros them after its pooling work. This keeps every call identical.
__global__ void k_count(const int* __restrict__ dst, const int* __restrict__ et) {
    int e = blockIdx.x * blockDim.x + threadIdx.x;
    if (e < EE) {
        int d = dst[e];
        if (et[e] == 0) atomicAdd(&g_cntd[d], 1);
        else            atomicAdd(&g_cntc[d], 1);
    }
}

// single-block exclusive scan over degrees -> rowptr (+ cursor copy)
__global__ void __launch_bounds__(1024) k_scan() {
    __shared__ int warp_sums[32];
    __shared__ int s_carry;
    int tid = threadIdx.x;
    int lane = tid & 31, wid = tid >> 5;
    if (tid == 0) s_carry = 0;
    __syncthreads();
    for (int base = 0; base < NN; base += 1024) {
        int i = base + tid;
        int v = (i < NN) ? (g_cntd[i] + g_cntc[i]) : 0;
        int x = v;
        #pragma unroll
        for (int off = 1; off < 32; off <<= 1) {
            int y = __shfl_up_sync(0xffffffffu, x, off);
            if (lane >= off) x += y;
        }
        if (lane == 31) warp_sums[wid] = x;
        __syncthreads();
        if (tid < 32) {
            int w = warp_sums[tid];
            #pragma unroll
            for (int off = 1; off < 32; off <<= 1) {
                int y = __shfl_up_sync(0xffffffffu, w, off);
                if (tid >= off) w += y;
            }
            warp_sums[tid] = w;
        }
        __syncthreads();
        int woff = (wid > 0) ? warp_sums[wid - 1] : 0;
        int incl = x + woff;
        if (i < NN) {
            int rp = s_carry + incl - v;
            g_rowptr[i] = rp;
            g_cursor[i] = rp;
        }
        int total = warp_sums[31];
        __syncthreads();
        if (tid == 0) s_carry += total;
        __syncthreads();
    }
    if (tid == 0) g_rowptr[NN] = s_carry;
}

__global__ void k_fill(const int* __restrict__ src, const int* __restrict__ dst,
                       const int* __restrict__ et) {
    int e = blockIdx.x * blockDim.x + threadIdx.x;
    if (e < EE) {
        int d = dst[e];
        int pos = atomicAdd(&g_cursor[d], 1);
        g_edge[pos] = (unsigned int)src[e] | ((unsigned int)et[e] << 31);
    }
}

// ---------------- edge aggregation: warp per dst node ----------------
__global__ void __launch_bounds__(256) k_aggregate(const float* __restrict__ X) {
    int w = (blockIdx.x * blockDim.x + threadIdx.x) >> 5;
    int lane = threadIdx.x & 31;
    if (w >= NN) return;
    int beg = g_rowptr[w], end = g_rowptr[w + 1];
    const float4* X4 = (const float4*)X;
    float4 ad = make_float4(0.f, 0.f, 0.f, 0.f);
    float4 ac = make_float4(0.f, 0.f, 0.f, 0.f);
    int j = beg;
    for (; j + 1 < end; j += 2) {
        unsigned int e0 = g_edge[j];
        unsigned int e1 = g_edge[j + 1];
        float4 v0 = __ldg(X4 + (int)(e0 & 0x7fffffffu) * 32 + lane);
        float4 v1 = __ldg(X4 + (int)(e1 & 0x7fffffffu) * 32 + lane);
        if (e0 >> 31) { ac.x += v0.x; ac.y += v0.y; ac.z += v0.z; ac.w += v0.w; }
        else          { ad.x += v0.x; ad.y += v0.y; ad.z += v0.z; ad.w += v0.w; }
        if (e1 >> 31) { ac.x += v1.x; ac.y += v1.y; ac.z += v1.z; ac.w += v1.w; }
        else          { ad.x += v1.x; ad.y += v1.y; ad.z += v1.z; ad.w += v1.w; }
    }
    if (j < end) {
        unsigned int e0 = g_edge[j];
        float4 v0 = __ldg(X4 + (int)(e0 & 0x7fffffffu) * 32 + lane);
        if (e0 >> 31) { ac.x += v0.x; ac.y += v0.y; ac.z += v0.z; ac.w += v0.w; }
        else          { ad.x += v0.x; ad.y += v0.y; ad.z += v0.z; ad.w += v0.w; }
    }
    ((float4*)g_Sd)[w * 32 + lane] = ad;
    ((float4*)g_Sc)[w * 32 + lane] = ac;
}

// ---------------- fused triple GEMM + bias + relu (round-1 champion) ----------
// X' = relu(Sd@Wd + Sc@Wc + X@Ws + cntd*bd + cntc*bc + bs)
// block: 256 threads, 32 rows x 128 cols. thread (tx,ty): cols tx*4..+4, rows ty*4..+4
__global__ void __launch_bounds__(256) k_gemm(
    const float* __restrict__ Xin,
    const float* __restrict__ Wd, const float* __restrict__ bd,
    const float* __restrict__ Wc, const float* __restrict__ bc,
    const float* __restrict__ Ws, const float* __restrict__ bs,
    float* __restrict__ Y)
{
    __shared__ __align__(16) float sX[3][DD][32]; // [mat][k][row] transposed tiles, 48KB
    int tid = threadIdx.x;
    int rowbase = blockIdx.x * 32;

    // load tiles (transposed: k-major so main loop can LDS.64 row pairs)
    {
        int r = tid & 31;
        int kq = tid >> 5; // 0..7, covers 16 k each
        int row = rowbase + r;
        const float* srcs[3] = { g_Sd, g_Sc, Xin };
        #pragma unroll
        for (int m = 0; m < 3; m++) {
            #pragma unroll
            for (int q = 0; q < 4; q++) {
                float4 a;
                if (row < NN) a = __ldg((const float4*)(srcs[m] + row * DD) + kq * 4 + q);
                else          a = make_float4(0.f, 0.f, 0.f, 0.f);
                int k0 = kq * 16 + q * 4;
                sX[m][k0 + 0][r] = a.x;
                sX[m][k0 + 1][r] = a.y;
                sX[m][k0 + 2][r] = a.z;
                sX[m][k0 + 3][r] = a.w;
            }
        }
    }
    __syncthreads();

    int tx = tid & 31;
    int ty = tid >> 5;
    const float4* W4[3] = { (const float4*)Wd, (const float4*)Wc, (const float4*)Ws };
    unsigned long long acc[2][4] = { {0ull,0ull,0ull,0ull}, {0ull,0ull,0ull,0ull} };

    #pragma unroll 4
    for (int k = 0; k < DD; k++) {
        #pragma unroll
        for (int m = 0; m < 3; m++) {
            float4 wv = __ldg(W4[m] + k * 32 + tx);
            unsigned long long w0 = pk2(wv.x), w1 = pk2(wv.y);
            unsigned long long w2 = pk2(wv.z), w3 = pk2(wv.w);
            const unsigned long long* xp =
                (const unsigned long long*)&sX[m][k][0];
            unsigned long long xa = xp[ty * 2];     // rows (ty*4, ty*4+1)
            unsigned long long xb = xp[ty * 2 + 1]; // rows (ty*4+2, ty*4+3)
            acc[0][0] = ffma2(xa, w0, acc[0][0]);
            acc[0][1] = ffma2(xa, w1, acc[0][1]);
            acc[0][2] = ffma2(xa, w2, acc[0][2]);
            acc[0][3] = ffma2(xa, w3, acc[0][3]);
            acc[1][0] = ffma2(xb, w0, acc[1][0]);
            acc[1][1] = ffma2(xb, w1, acc[1][1]);
            acc[1][2] = ffma2(xb, w2, acc[1][2]);
            acc[1][3] = ffma2(xb, w3, acc[1][3]);
        }
    }

    float4 bdv = __ldg((const float4*)bd + tx);
    float4 bcv = __ldg((const float4*)bc + tx);
    float4 bsv = __ldg((const float4*)bs + tx);
    #pragma unroll
    for (int j = 0; j < 4; j++) {
        int row = rowbase + ty * 4 + j;
        if (row >= NN) continue;
        int p = j >> 1, h = j & 1;
        float2 c0 = *(float2*)&acc[p][0];
        float2 c1 = *(float2*)&acc[p][1];
        float2 c2 = *(float2*)&acc[p][2];
        float2 c3 = *(float2*)&acc[p][3];
        float4 o;
        o.x = h ? c0.y : c0.x;
        o.y = h ? c1.y : c1.x;
        o.z = h ? c2.y : c2.x;
        o.w = h ? c3.y : c3.x;
        float cd = (float)g_cntd[row];
        float cc = (float)g_cntc[row];
        o.x = fmaxf(fmaf(cd, bdv.x, fmaf(cc, bcv.x, o.x + bsv.x)), 0.f);
        o.y = fmaxf(fmaf(cd, bdv.y, fmaf(cc, bcv.y, o.y + bsv.y)), 0.f);
        o.z = fmaxf(fmaf(cd, bdv.z, fmaf(cc, bcv.z, o.z + bsv.z)), 0.f);
        o.w = fmaxf(fmaf(cd, bdv.w, fmaf(cc, bcv.w, o.w + bsv.w)), 0.f);
        ((float4*)Y)[row * 32 + tx] = o;
    }
}

// ---------------- mean pool per graph + count re-zero (last launch) ----------
__global__ void __launch_bounds__(DD) k_pool(const float* __restrict__ X,
                                             const int* __restrict__ batch,
                                             float* __restrict__ out) {
    int g = blockIdx.x;
    int c = threadIdx.x;
    int lo = 0, hi = NN;
    while (lo < hi) { int m = (lo + hi) >> 1; if (batch[m] < g) lo = m + 1; else hi = m; }
    int start = lo;
    lo = start; hi = NN;
    while (lo < hi) { int m = (lo + hi) >> 1; if (batch[m] < g + 1) lo = m + 1; else hi = m; }
    int end = lo;

    float s0 = 0.f, s1 = 0.f, s2 = 0.f, s3 = 0.f;
    int n = start;
    for (; n + 3 < end; n += 4) {
        s0 += X[(n + 0) * DD + c];
        s1 += X[(n + 1) * DD + c];
        s2 += X[(n + 2) * DD + c];
        s3 += X[(n + 3) * DD + c];
    }
    for (; n < end; n++) s0 += X[n * DD + c];
    float s = (s0 + s1) + (s2 + s3);
    float cnt = (float)(end - start);
    out[g * DD + c] = s / fmaxf(cnt, 1.0f);

    // restore count arrays to zero for the next call (grid-stride)
    for (int i = g * DD + c; i < NN; i += GG * DD) {
        g_cntd[i] = 0;
        g_cntc[i] = 0;
    }
}

// ---------------- launch ----------------
extern "C" void kernel_launch(void* const* d_in, const int* in_sizes, int n_in,
                              void* d_out, int out_size) {
    const float* X  = (const float*)d_in[0];
    const float* Wd = (const float*)d_in[1];
    const float* bd = (const float*)d_in[2];
    const float* Wc = (const float*)d_in[3];
    const float* bc = (const float*)d_in[4];
    const float* Ws = (const float*)d_in[5];
    const float* bs = (const float*)d_in[6];
    const int* ei   = (const int*)d_in[7];
    const int* et   = (const int*)d_in[8];
    const int* bid  = (const int*)d_in[9];
    const int* srcp = ei;
    const int* dstp = ei + EE;

    void* pA = nullptr;
    void* pB = nullptr;
    cudaGetSymbolAddress(&pA, g_bufA);
    cudaGetSymbolAddress(&pB, g_bufB);
    float* A = (float*)pA;
    float* B = (float*)pB;

    // CSR build (counts arrive zeroed; k_pool re-zeros them at the end)
    k_count<<<(EE + 255) / 256, 256>>>(dstp, et);        // my launch 0
    k_scan<<<1, 1024>>>();                                // 1
    k_fill<<<(EE + 255) / 256, 256>>>(srcp, dstp, et);    // 2

    const float* cur = X;
    float* outs[3] = { A, B, A };
    for (int l = 0; l < LL; l++) {
        k_aggregate<<<(NN * 32 + 255) / 256, 256>>>(cur); // 3 (ncu window, l=0)
        k_gemm<<<(NN + 31) / 32, 256>>>(cur,
                                        Wd + l * DD * DD, bd + l * DD,
                                        Wc + l * DD * DD, bc + l * DD,
                                        Ws + l * DD * DD, bs + l * DD,
                                        outs[l]);
        cur = outs[l];
    }
    k_pool<<<GG, DD>>>(cur, bid, (float*)d_out);
}